// round 15
// baseline (speedup 1.0000x reference)
#include <cuda_runtime.h>
#include <cuda_bf16.h>
#include <cuda_fp16.h>
#include <cstdint>

// ---------------------------------------------------------------------------
// HungarianMatcher cost matrix. B=16 Q=900 C=91 T=4800, out [14400,4800] f32.
//
// R15 = R13 (best, 93.9us; R14's de-unroll + FFMA-imm reverted) + ONE change:
//  - two-reciprocal giou tail: -2*giou = 2 - 2*inter*rcp(uni) - 2*uni*rcp(enc)
//    (+2 baked into focal). Replaces 5 FMUL + 2 FFMA + 1 MUFU with
//    3 FMUL + 2 FFMA + 2 MUFU: -1 issue slot and -4 fma-pipe cycles per
//    element. Model: fma pipe (rt=2) was the binder at ~36 cyc per 29 slots
//    (issue cap 0.80, measured 0.73); this lifts the cap to ~0.87 by moving
//    work to the idle MUFU pipe (rt=8, demand stays well under capacity).
//  - unchanged: fp16 quad-interleaved focal (LDG.64 per class x row-quad,
//    depth-1 prefetch, compile-time last-iter skip), negated/packed giou
//    (f32x2 adds, FMNMX on alu pipe), f32x2 L1 diffs, no eps clamps,
//    streaming stores, merged prep, exact tiling 64 rows x 192 targets.
// ---------------------------------------------------------------------------

#define BQ_MAX   14400
#define T_MAX    4800
#define NCLS     91
#define CP       96            // class stride; fp16 quad block = 4*CP*2 = 768B

__device__ __align__(128) __half g_Fh[BQ_MAX * CP];  // quad-interleaved fp16
__device__ float4 g_tgtA[T_MAX];        // -5*cxcywh  (negated)
__device__ float4 g_tgtB[T_MAX];        // {x0, y0, -x1, -y1}
__device__ float4 g_tgtE[T_MAX];        // {w, h, area, asfloat(cls*8)}
__device__ float4 g_rowA[BQ_MAX];       // +5*cxcywh
__device__ float4 g_rowB[BQ_MAX];       // {x0, y0, -x1, -y1}
__device__ float4 g_rowE[BQ_MAX];       // {w, h, area, 0}

__device__ __forceinline__ float frcp_approx(float x) {
    float r;
    asm("rcp.approx.f32 %0, %1;" : "=f"(r) : "f"(x));
    return r;
}

#define ADD_F32X2(out, a, b) \
    asm("add.rn.f32x2 %0, %1, %2;" : "=l"(out) : "l"(a), "l"(b))
#define UNPACK2F(lo, hi, in) \
    asm("mov.b64 {%0, %1}, %2;" : "=f"(lo), "=f"(hi) : "l"(in))
#define PACK2F(out, lo, hi) \
    asm("mov.b64 %0, {%1, %2};" : "=l"(out) : "f"(lo), "f"(hi))

// --------------------- merged prep (single launch) --------------------------
__global__ void prep_all(const float* __restrict__ logits,
                         const float* __restrict__ pboxes,
                         const float* __restrict__ tboxes,
                         const int*   __restrict__ ids,
                         int BQ, int C, int T) {
    int i = blockIdx.x * blockDim.x + threadIdx.x;

    if (i < BQ * C) {
        int row = i / C;
        int c   = i - row * C;
        float x = logits[i];
        float e = __expf(-x);
        float inv = frcp_approx(1.0f + e);
        float p = inv;          // sigmoid
        float q = e * inv;      // 1 - sigmoid, no cancellation
        float lp = __logf(p + 1e-8f);
        float lq = __logf(q + 1e-8f);
        // 2*(pos-neg) + 2   (the +2 from the giou rewrite)
        float F2 = -0.5f * q * q * lp + 1.5f * p * p * lq + 2.0f;
        g_Fh[(row >> 2) * (4 * CP) + c * 4 + (row & 3)] = __float2half_rn(F2);
    }

    if (i < BQ) {
        float4 b = reinterpret_cast<const float4*>(pboxes)[i];  // cx,cy,w,h
        g_rowA[i] = make_float4(5.f*b.x, 5.f*b.y, 5.f*b.z, 5.f*b.w);
        float x0 = b.x - 0.5f*b.z, y0 = b.y - 0.5f*b.w;
        float x1 = b.x + 0.5f*b.z, y1 = b.y + 0.5f*b.w;
        float w = x1 - x0, h = y1 - y0;
        g_rowB[i] = make_float4(x0, y0, -x1, -y1);
        g_rowE[i] = make_float4(w, h, w * h, 0.f);
    }

    if (i < T) {
        float4 b = reinterpret_cast<const float4*>(tboxes)[i];
        g_tgtA[i] = make_float4(-5.f*b.x, -5.f*b.y, -5.f*b.z, -5.f*b.w);
        float x0 = b.x - 0.5f*b.z, y0 = b.y - 0.5f*b.w;
        float x1 = b.x + 0.5f*b.z, y1 = b.y + 0.5f*b.w;
        float w = x1 - x0, h = y1 - y0;
        g_tgtB[i] = make_float4(x0, y0, -x1, -y1);
        // class byte offset within an fp16 quad block: cls * 8
        g_tgtE[i] = make_float4(w, h, w * h, __int_as_float((ids[i] - 1) * 8));
    }
}

// ---------------------------- main kernel -----------------------------------
// Block 256 threads = 64 rows x 192 targets (4800 = 25*192, 14400 = 225*64).
//   rr = tid>>6 -> rows row0 + rr*16 (four quads); tt = tid&63 -> 3 targets
#define ROW_TILE 64
#define TGT_TILE 192
#define RPT      16
#define QSTRIDE  (4 * CP * 2)   // bytes between consecutive row-quads

__global__ void __launch_bounds__(256, 3)
cost_kernel(float* __restrict__ out, int T) {
    const int tid  = threadIdx.x;
    const int tt   = tid & 63;
    const int rr   = tid >> 6;
    const int row0 = blockIdx.y * ROW_TILE + rr * RPT;   // multiple of 16
    const int base = blockIdx.x * TGT_TILE + tt;

    // ---- 3 targets in registers (coalesced loads) ----
    unsigned long long taL[3], taH[3];     // packed (-5cx,-5cy) / (-5w,-5h)
    float4 tb[3];
    unsigned long long tE_wh[3];           // packed (wt, ht)
    float  tarea[3];
    int    qoff[3];                        // 32-bit byte offset into g_Fh
    {
        const int qbase = (row0 >> 2) * QSTRIDE;
        #pragma unroll
        for (int k = 0; k < 3; ++k) {
            const int j = base + (k << 6);
            ulonglong2 a = *reinterpret_cast<const ulonglong2*>(&g_tgtA[j]);
            taL[k] = a.x;  taH[k] = a.y;
            tb[k]  = g_tgtB[j];
            ulonglong2 e = *reinterpret_cast<const ulonglong2*>(&g_tgtE[j]);
            tE_wh[k] = e.x;                            // (w, h) packed
            float2 ez = *reinterpret_cast<const float2*>(&e.y);
            tarea[k] = ez.x;
            qoff[k]  = qbase + __float_as_int(ez.y);
        }
    }

    const char* fbase = reinterpret_cast<const char*>(g_Fh);
    float* dstRow = out + (size_t)row0 * T + base;

    // depth-1 pipelined gathers: raw = quad qp, nxt = quad qp+1
    uint2 raw[3];
    #pragma unroll
    for (int k = 0; k < 3; ++k)
        raw[k] = __ldg(reinterpret_cast<const uint2*>(fbase + qoff[k]));

    #pragma unroll
    for (int qp = 0; qp < RPT / 4; ++qp) {
        uint2 nxt[3];
        if (qp < RPT / 4 - 1) {            // compile-time in unrolled body
            #pragma unroll
            for (int k = 0; k < 3; ++k)
                nxt[k] = __ldg(reinterpret_cast<const uint2*>(
                             fbase + qoff[k] + (qp + 1) * QSTRIDE));
        }

        // convert current quad's fp16 focal values (contain focal*2 + 2)
        float4 f4[3];
        #pragma unroll
        for (int k = 0; k < 3; ++k) {
            float2 lo = __half22float2(*reinterpret_cast<__half2*>(&raw[k].x));
            float2 hi = __half22float2(*reinterpret_cast<__half2*>(&raw[k].y));
            f4[k] = make_float4(lo.x, lo.y, hi.x, hi.y);
        }

        #pragma unroll
        for (int r4 = 0; r4 < 4; ++r4) {
            const int row = row0 + qp * 4 + r4;
            // warp-uniform row loads (broadcast, 1 wavefront each)
            const ulonglong2 rA2 =
                *reinterpret_cast<const ulonglong2*>(&g_rowA[row]);
            const float4 rB = g_rowB[row];       // {x0, y0, -x1, -y1}
            const ulonglong2 rE2 =
                *reinterpret_cast<const ulonglong2*>(&g_rowE[row]);
            const float rarea =
                reinterpret_cast<const float2*>(&rE2.y)->x;

            #pragma unroll
            for (int k = 0; k < 3; ++k) {
                const float f2 = reinterpret_cast<const float*>(&f4[k])[r4];

                // ---- 5*L1: packed diffs (rA=+5c, ta=-5c) ----
                unsigned long long dxy, dzw;
                ADD_F32X2(dxy, rA2.x, taL[k]);
                ADD_F32X2(dzw, rA2.y, taH[k]);
                float d0, d1, d2, d3;
                UNPACK2F(d0, d1, dxy);
                UNPACK2F(d2, d3, dzw);
                float bx = (fabsf(d0) + fabsf(d1)) + (fabsf(d2) + fabsf(d3));

                // ---- intersection via negated-sw form (FMNMX on ALU pipe) --
                float Mx = fmaxf(rB.x, tb[k].x);     // max(x0)
                float My = fmaxf(rB.y, tb[k].y);     // max(y0)
                float Nx = fmaxf(rB.z, tb[k].z);     // max(-x1) = -min(x1)
                float Ny = fmaxf(rB.w, tb[k].w);
                unsigned long long Mxy, Nxy, nswh;
                PACK2F(Mxy, Mx, My);
                PACK2F(Nxy, Nx, Ny);
                ADD_F32X2(nswh, Mxy, Nxy);           // (-sw, -sh)
                float nsw, nsh;
                UNPACK2F(nsw, nsh, nswh);
                float niw = fminf(nsw, 0.0f);        // = -iw   (ALU)
                float nih = fminf(nsh, 0.0f);        // = -ih   (ALU)
                float inter = niw * nih;             // iw*ih

                // ---- enclosing, packed: encwh = (wr+wt) + (-sw,-sh) ----
                unsigned long long wsum, encwh;
                ADD_F32X2(wsum, rE2.x, tE_wh[k]);    // (wr+wt, hr+ht)
                ADD_F32X2(encwh, wsum, nswh);
                float encw, ench;
                UNPACK2F(encw, ench, encwh);
                float enc = encw * ench;

                // uni >= max(area_r, area_t) > 0: no clamps needed
                float uni = (rarea + tarea[k]) - inter;

                // -2*giou = 2 - 2*inter/uni - 2*uni/enc ; +2 baked in f2.
                // Two MUFU rcps instead of FMUL-heavy single-rcp tail:
                float rcpu = frcp_approx(uni);
                float rcpe = frcp_approx(enc);
                float t  = inter * rcpu;
                float t2 = fmaf(uni, rcpe, t);
                float res = fmaf(t2, -2.0f, f2 + bx);
                __stcs(dstRow + (k << 6), res);      // STG.CS, coalesced
            }
            dstRow += T;   // walk rows (single IADD)
        }

        #pragma unroll
        for (int k = 0; k < 3; ++k) raw[k] = nxt[k];
    }
}

// ---------------------------------------------------------------------------
extern "C" void kernel_launch(void* const* d_in, const int* in_sizes, int n_in,
                              void* d_out, int out_size) {
    const float* pred_logits = (const float*)d_in[0];
    const float* pred_boxes  = (const float*)d_in[1];
    const int*   tgt_ids     = (const int*)d_in[2];
    const float* tgt_boxes   = (const float*)d_in[3];
    float* out = (float*)d_out;

    const int BQ = in_sizes[1] / 4;          // 14400
    const int C  = in_sizes[0] / BQ;         // 91
    const int T  = in_sizes[2];              // 4800

    prep_all<<<(BQ * C + 255) / 256, 256>>>(pred_logits, pred_boxes,
                                            tgt_boxes, tgt_ids, BQ, C, T);

    // exact tiling: 4800 = 25*192, 14400 = 225*64
    dim3 grid(T / TGT_TILE, BQ / ROW_TILE);
    cost_kernel<<<grid, 256>>>(out, T);
}

// round 16
// speedup vs baseline: 1.1060x; 1.1060x over previous
#include <cuda_runtime.h>
#include <cuda_bf16.h>
#include <cuda_fp16.h>
#include <cstdint>

// ---------------------------------------------------------------------------
// HungarianMatcher cost matrix. B=16 Q=900 C=91 T=4800, out [14400,4800] f32.
//
// R16 = R13 (best, 93.9us; R14/R15 micro-changes reverted) + wider target
// amortization:
//  - 5 targets per thread (TGT_TILE=320, 4800 = 15*320 exact): row loads
//    (3 LDG per row, the largest per-element memory item at 1.0 slot/elem)
//    amortize to 0.6 slot/elem, and each row step now has 5 independent
//    elements of math to hide the row-load latency
//  - __launch_bounds__(256,2): 128-reg budget for the wider live state
//    (ptxas gets freedom to hoist/schedule; occupancy 16 warps/SM traded
//    for 5/3x per-thread ILP — same trade that won in R7)
//  - unchanged: fp16 quad-interleaved focal (LDG.64 per class x row-quad,
//    depth-1 prefetch), negated/packed giou (f32x2 adds, FMNMX on alu),
//    f32x2 L1 diffs, uni^2 single-rcp tail (+2 baked into focal), no eps
//    clamps, streaming stores, merged prep, exact tiling 64 rows x 320 tgts
// ---------------------------------------------------------------------------

#define BQ_MAX   14400
#define T_MAX    4800
#define NCLS     91
#define CP       96            // class stride; fp16 quad block = 4*CP*2 = 768B

__device__ __align__(128) __half g_Fh[BQ_MAX * CP];  // quad-interleaved fp16
__device__ float4 g_tgtA[T_MAX];        // -5*cxcywh  (negated)
__device__ float4 g_tgtB[T_MAX];        // {x0, y0, -x1, -y1}
__device__ float4 g_tgtE[T_MAX];        // {w, h, area, asfloat(cls*8)}
__device__ float4 g_rowA[BQ_MAX];       // +5*cxcywh
__device__ float4 g_rowB[BQ_MAX];       // {x0, y0, -x1, -y1}
__device__ float4 g_rowE[BQ_MAX];       // {w, h, area, 0}

__device__ __forceinline__ float frcp_approx(float x) {
    float r;
    asm("rcp.approx.f32 %0, %1;" : "=f"(r) : "f"(x));
    return r;
}

#define ADD_F32X2(out, a, b) \
    asm("add.rn.f32x2 %0, %1, %2;" : "=l"(out) : "l"(a), "l"(b))
#define UNPACK2F(lo, hi, in) \
    asm("mov.b64 {%0, %1}, %2;" : "=f"(lo), "=f"(hi) : "l"(in))
#define PACK2F(out, lo, hi) \
    asm("mov.b64 %0, {%1, %2};" : "=l"(out) : "f"(lo), "f"(hi))

// --------------------- merged prep (single launch) --------------------------
__global__ void prep_all(const float* __restrict__ logits,
                         const float* __restrict__ pboxes,
                         const float* __restrict__ tboxes,
                         const int*   __restrict__ ids,
                         int BQ, int C, int T) {
    int i = blockIdx.x * blockDim.x + threadIdx.x;

    if (i < BQ * C) {
        int row = i / C;
        int c   = i - row * C;
        float x = logits[i];
        float e = __expf(-x);
        float inv = frcp_approx(1.0f + e);
        float p = inv;          // sigmoid
        float q = e * inv;      // 1 - sigmoid, no cancellation
        float lp = __logf(p + 1e-8f);
        float lq = __logf(q + 1e-8f);
        // 2*(pos-neg) + 2   (the +2 from the uni^2 giou rewrite)
        float F2 = -0.5f * q * q * lp + 1.5f * p * p * lq + 2.0f;
        g_Fh[(row >> 2) * (4 * CP) + c * 4 + (row & 3)] = __float2half_rn(F2);
    }

    if (i < BQ) {
        float4 b = reinterpret_cast<const float4*>(pboxes)[i];  // cx,cy,w,h
        g_rowA[i] = make_float4(5.f*b.x, 5.f*b.y, 5.f*b.z, 5.f*b.w);
        float x0 = b.x - 0.5f*b.z, y0 = b.y - 0.5f*b.w;
        float x1 = b.x + 0.5f*b.z, y1 = b.y + 0.5f*b.w;
        float w = x1 - x0, h = y1 - y0;
        g_rowB[i] = make_float4(x0, y0, -x1, -y1);
        g_rowE[i] = make_float4(w, h, w * h, 0.f);
    }

    if (i < T) {
        float4 b = reinterpret_cast<const float4*>(tboxes)[i];
        g_tgtA[i] = make_float4(-5.f*b.x, -5.f*b.y, -5.f*b.z, -5.f*b.w);
        float x0 = b.x - 0.5f*b.z, y0 = b.y - 0.5f*b.w;
        float x1 = b.x + 0.5f*b.z, y1 = b.y + 0.5f*b.w;
        float w = x1 - x0, h = y1 - y0;
        g_tgtB[i] = make_float4(x0, y0, -x1, -y1);
        // class byte offset within an fp16 quad block: cls * 8
        g_tgtE[i] = make_float4(w, h, w * h, __int_as_float((ids[i] - 1) * 8));
    }
}

// ---------------------------- main kernel -----------------------------------
// Block 256 threads = 64 rows x 320 targets (4800 = 15*320, 14400 = 225*64).
//   rr = tid>>6 -> rows row0 + rr*16 (four quads); tt = tid&63 -> 5 targets
#define ROW_TILE 64
#define TGT_TILE 320
#define K        5
#define RPT      16
#define QSTRIDE  (4 * CP * 2)   // bytes between consecutive row-quads

__global__ void __launch_bounds__(256, 2)
cost_kernel(float* __restrict__ out, int T) {
    const int tid  = threadIdx.x;
    const int tt   = tid & 63;
    const int rr   = tid >> 6;
    const int row0 = blockIdx.y * ROW_TILE + rr * RPT;   // multiple of 16
    const int base = blockIdx.x * TGT_TILE + tt;

    // ---- 5 targets in registers (coalesced loads) ----
    unsigned long long taL[K], taH[K];     // packed (-5cx,-5cy) / (-5w,-5h)
    float4 tb[K];
    unsigned long long tE_wh[K];           // packed (wt, ht)
    float  tarea[K];
    int    qoff[K];                        // 32-bit byte offset into g_Fh
    {
        const int qbase = (row0 >> 2) * QSTRIDE;
        #pragma unroll
        for (int k = 0; k < K; ++k) {
            const int j = base + (k << 6);
            ulonglong2 a = *reinterpret_cast<const ulonglong2*>(&g_tgtA[j]);
            taL[k] = a.x;  taH[k] = a.y;
            tb[k]  = g_tgtB[j];
            ulonglong2 e = *reinterpret_cast<const ulonglong2*>(&g_tgtE[j]);
            tE_wh[k] = e.x;                            // (w, h) packed
            float2 ez = *reinterpret_cast<const float2*>(&e.y);
            tarea[k] = ez.x;
            qoff[k]  = qbase + __float_as_int(ez.y);
        }
    }

    const char* fbase = reinterpret_cast<const char*>(g_Fh);
    float* dstRow = out + (size_t)row0 * T + base;

    // depth-1 pipelined gathers: raw = quad qp, nxt = quad qp+1
    uint2 raw[K];
    #pragma unroll
    for (int k = 0; k < K; ++k)
        raw[k] = __ldg(reinterpret_cast<const uint2*>(fbase + qoff[k]));

    #pragma unroll
    for (int qp = 0; qp < RPT / 4; ++qp) {
        uint2 nxt[K];
        if (qp < RPT / 4 - 1) {            // compile-time in unrolled body
            #pragma unroll
            for (int k = 0; k < K; ++k)
                nxt[k] = __ldg(reinterpret_cast<const uint2*>(
                             fbase + qoff[k] + (qp + 1) * QSTRIDE));
        }

        // convert current quad's fp16 focal values (contain focal*2 + 2)
        float4 f4[K];
        #pragma unroll
        for (int k = 0; k < K; ++k) {
            float2 lo = __half22float2(*reinterpret_cast<__half2*>(&raw[k].x));
            float2 hi = __half22float2(*reinterpret_cast<__half2*>(&raw[k].y));
            f4[k] = make_float4(lo.x, lo.y, hi.x, hi.y);
        }

        #pragma unroll
        for (int r4 = 0; r4 < 4; ++r4) {
            const int row = row0 + qp * 4 + r4;
            // warp-uniform row loads (broadcast, 1 wavefront each),
            // amortized over K=5 elements of math
            const ulonglong2 rA2 =
                *reinterpret_cast<const ulonglong2*>(&g_rowA[row]);
            const float4 rB = g_rowB[row];       // {x0, y0, -x1, -y1}
            const ulonglong2 rE2 =
                *reinterpret_cast<const ulonglong2*>(&g_rowE[row]);
            const float rarea =
                reinterpret_cast<const float2*>(&rE2.y)->x;

            #pragma unroll
            for (int k = 0; k < K; ++k) {
                const float f2 = reinterpret_cast<const float*>(&f4[k])[r4];

                // ---- 5*L1: packed diffs (rA=+5c, ta=-5c) ----
                unsigned long long dxy, dzw;
                ADD_F32X2(dxy, rA2.x, taL[k]);
                ADD_F32X2(dzw, rA2.y, taH[k]);
                float d0, d1, d2, d3;
                UNPACK2F(d0, d1, dxy);
                UNPACK2F(d2, d3, dzw);
                float bx = (fabsf(d0) + fabsf(d1)) + (fabsf(d2) + fabsf(d3));

                // ---- intersection via negated-sw form (FMNMX on ALU pipe) --
                float Mx = fmaxf(rB.x, tb[k].x);     // max(x0)
                float My = fmaxf(rB.y, tb[k].y);     // max(y0)
                float Nx = fmaxf(rB.z, tb[k].z);     // max(-x1) = -min(x1)
                float Ny = fmaxf(rB.w, tb[k].w);
                unsigned long long Mxy, Nxy, nswh;
                PACK2F(Mxy, Mx, My);
                PACK2F(Nxy, Nx, Ny);
                ADD_F32X2(nswh, Mxy, Nxy);           // (-sw, -sh)
                float nsw, nsh;
                UNPACK2F(nsw, nsh, nswh);
                float niw = fminf(nsw, 0.0f);        // = -iw   (ALU)
                float nih = fminf(nsh, 0.0f);        // = -ih   (ALU)
                float inter = niw * nih;             // iw*ih

                // ---- enclosing, packed: encwh = (wr+wt) + (-sw,-sh) ----
                unsigned long long wsum, encwh;
                ADD_F32X2(wsum, rE2.x, tE_wh[k]);    // (wr+wt, hr+ht)
                ADD_F32X2(encwh, wsum, nswh);
                float encw, ench;
                UNPACK2F(encw, ench, encwh);
                float enc = encw * ench;

                // uni >= max(area_r, area_t) > 0: no clamps needed
                float uni = (rarea + tarea[k]) - inter;

                // -2*giou = 2 - 2*(inter*enc + uni^2)/(uni*enc); +2 in f2
                float num = fmaf(uni, uni, inter * enc);
                float inv = frcp_approx(uni * enc);

                float res = fmaf(num * inv, -2.0f, f2 + bx);
                __stcs(dstRow + (k << 6), res);      // STG.CS, coalesced
            }
            dstRow += T;   // walk rows (single IADD)
        }

        #pragma unroll
        for (int k = 0; k < K; ++k) raw[k] = nxt[k];
    }
}

// ---------------------------------------------------------------------------
extern "C" void kernel_launch(void* const* d_in, const int* in_sizes, int n_in,
                              void* d_out, int out_size) {
    const float* pred_logits = (const float*)d_in[0];
    const float* pred_boxes  = (const float*)d_in[1];
    const int*   tgt_ids     = (const int*)d_in[2];
    const float* tgt_boxes   = (const float*)d_in[3];
    float* out = (float*)d_out;

    const int BQ = in_sizes[1] / 4;          // 14400
    const int C  = in_sizes[0] / BQ;         // 91
    const int T  = in_sizes[2];              // 4800

    prep_all<<<(BQ * C + 255) / 256, 256>>>(pred_logits, pred_boxes,
                                            tgt_boxes, tgt_ids, BQ, C, T);

    // exact tiling: 4800 = 15*320, 14400 = 225*64
    dim3 grid(T / TGT_TILE, BQ / ROW_TILE);
    cost_kernel<<<grid, 256>>>(out, T);
}

// round 17
// speedup vs baseline: 1.1151x; 1.0082x over previous
#include <cuda_runtime.h>
#include <cuda_bf16.h>
#include <cuda_fp16.h>
#include <cstdint>

// ---------------------------------------------------------------------------
// HungarianMatcher cost matrix. B=16 Q=900 C=91 T=4800, out [14400,4800] f32.
//
// R17 = R13 cost_kernel (best, 93.9us — R14/R15/R16 alternatives all reverted)
//       + division-free, write-coalesced prep:
//  - prep grid = row-quads (BQ/4 blocks x 384 threads), tid = c*4 + r:
//    focal write index = blockIdx.x*384 + tid -> perfectly sequential
//    halfword stores, no integer division, no index math
//  - spare threads (tid>=364) do row prep (4 rows/block) and target prep
//    (4 targets/block for the first T/4 blocks) in the same launch
//  - cost_kernel unchanged: fp16 quad-interleaved focal (LDG.64 per class x
//    row-quad, depth-1 prefetch), negated/packed giou (f32x2 adds, FMNMX on
//    alu), f32x2 L1 diffs, uni^2 single-rcp tail (+2 baked into focal),
//    no eps clamps, streaming stores, exact tiling 64 rows x 192 targets
// ---------------------------------------------------------------------------

#define BQ_MAX   14400
#define T_MAX    4800
#define NCLS     91
#define CP       96            // class stride; fp16 quad block = 4*CP*2 = 768B

__device__ __align__(128) __half g_Fh[BQ_MAX * CP];  // quad-interleaved fp16
__device__ float4 g_tgtA[T_MAX];        // -5*cxcywh  (negated)
__device__ float4 g_tgtB[T_MAX];        // {x0, y0, -x1, -y1}
__device__ float4 g_tgtE[T_MAX];        // {w, h, area, asfloat(cls*8)}
__device__ float4 g_rowA[BQ_MAX];       // +5*cxcywh
__device__ float4 g_rowB[BQ_MAX];       // {x0, y0, -x1, -y1}
__device__ float4 g_rowE[BQ_MAX];       // {w, h, area, 0}

__device__ __forceinline__ float frcp_approx(float x) {
    float r;
    asm("rcp.approx.f32 %0, %1;" : "=f"(r) : "f"(x));
    return r;
}

#define ADD_F32X2(out, a, b) \
    asm("add.rn.f32x2 %0, %1, %2;" : "=l"(out) : "l"(a), "l"(b))
#define UNPACK2F(lo, hi, in) \
    asm("mov.b64 {%0, %1}, %2;" : "=f"(lo), "=f"(hi) : "l"(in))
#define PACK2F(out, lo, hi) \
    asm("mov.b64 %0, {%1, %2};" : "=l"(out) : "f"(lo), "f"(hi))

// --------------------- prep: one launch, division-free -----------------------
// grid = BQ/4 blocks, block = 384 threads. tid = c*4 + r (c = class, r = row
// lane within the quad). Focal writes land at g_Fh[blockIdx.x*384 + tid]:
// fully sequential. Spare threads handle box/target prep.
__global__ void __launch_bounds__(384)
prep_all(const float* __restrict__ logits,
         const float* __restrict__ pboxes,
         const float* __restrict__ tboxes,
         const int*   __restrict__ ids,
         int C, int T) {
    const int tid = threadIdx.x;
    const int c   = tid >> 2;
    const int r   = tid & 3;
    const int qb  = blockIdx.x;

    if (c < NCLS) {
        const int row = (qb << 2) + r;
        float x = logits[row * C + c];
        float e = __expf(-x);
        float inv = frcp_approx(1.0f + e);
        float p = inv;          // sigmoid
        float q = e * inv;      // 1 - sigmoid, no cancellation
        float lp = __logf(p + 1e-8f);
        float lq = __logf(q + 1e-8f);
        // 2*(pos-neg) + 2   (the +2 from the uni^2 giou rewrite)
        float F2 = -0.5f * q * q * lp + 1.5f * p * p * lq + 2.0f;
        g_Fh[qb * (4 * CP) + tid] = __float2half_rn(F2);   // sequential
    } else {
        const int w = tid - (NCLS * 4);      // 0..19 spare threads
        if (w < 4) {
            const int i = (qb << 2) + w;     // row prep
            float4 b = reinterpret_cast<const float4*>(pboxes)[i];
            g_rowA[i] = make_float4(5.f*b.x, 5.f*b.y, 5.f*b.z, 5.f*b.w);
            float x0 = b.x - 0.5f*b.z, y0 = b.y - 0.5f*b.w;
            float x1 = b.x + 0.5f*b.z, y1 = b.y + 0.5f*b.w;
            float wd = x1 - x0, ht = y1 - y0;
            g_rowB[i] = make_float4(x0, y0, -x1, -y1);
            g_rowE[i] = make_float4(wd, ht, wd * ht, 0.f);
        } else if (w < 8) {
            const int t = (qb << 2) + (w - 4);   // target prep
            if (t < T) {
                float4 b = reinterpret_cast<const float4*>(tboxes)[t];
                g_tgtA[t] = make_float4(-5.f*b.x, -5.f*b.y, -5.f*b.z, -5.f*b.w);
                float x0 = b.x - 0.5f*b.z, y0 = b.y - 0.5f*b.w;
                float x1 = b.x + 0.5f*b.z, y1 = b.y + 0.5f*b.w;
                float wd = x1 - x0, ht = y1 - y0;
                g_tgtB[t] = make_float4(x0, y0, -x1, -y1);
                // class byte offset within an fp16 quad block: cls * 8
                g_tgtE[t] = make_float4(wd, ht, wd * ht,
                                        __int_as_float((ids[t] - 1) * 8));
            }
        }
    }
}

// ---------------------------- main kernel -----------------------------------
// Block 256 threads = 64 rows x 192 targets (4800 = 25*192, 14400 = 225*64).
//   rr = tid>>6 -> rows row0 + rr*16 (four quads); tt = tid&63 -> 3 targets
#define ROW_TILE 64
#define TGT_TILE 192
#define RPT      16
#define QSTRIDE  (4 * CP * 2)   // bytes between consecutive row-quads

__global__ void __launch_bounds__(256, 3)
cost_kernel(float* __restrict__ out, int T) {
    const int tid  = threadIdx.x;
    const int tt   = tid & 63;
    const int rr   = tid >> 6;
    const int row0 = blockIdx.y * ROW_TILE + rr * RPT;   // multiple of 16
    const int base = blockIdx.x * TGT_TILE + tt;

    // ---- 3 targets in registers (coalesced loads) ----
    unsigned long long taL[3], taH[3];     // packed (-5cx,-5cy) / (-5w,-5h)
    float4 tb[3];
    unsigned long long tE_wh[3];           // packed (wt, ht)
    float  tarea[3];
    int    qoff[3];                        // 32-bit byte offset into g_Fh
    {
        const int qbase = (row0 >> 2) * QSTRIDE;
        #pragma unroll
        for (int k = 0; k < 3; ++k) {
            const int j = base + (k << 6);
            ulonglong2 a = *reinterpret_cast<const ulonglong2*>(&g_tgtA[j]);
            taL[k] = a.x;  taH[k] = a.y;
            tb[k]  = g_tgtB[j];
            ulonglong2 e = *reinterpret_cast<const ulonglong2*>(&g_tgtE[j]);
            tE_wh[k] = e.x;                            // (w, h) packed
            float2 ez = *reinterpret_cast<const float2*>(&e.y);
            tarea[k] = ez.x;
            qoff[k]  = qbase + __float_as_int(ez.y);
        }
    }

    const char* fbase = reinterpret_cast<const char*>(g_Fh);
    float* dstRow = out + (size_t)row0 * T + base;

    // depth-1 pipelined gathers: raw = quad qp, nxt = quad qp+1
    uint2 raw[3];
    #pragma unroll
    for (int k = 0; k < 3; ++k)
        raw[k] = __ldg(reinterpret_cast<const uint2*>(fbase + qoff[k]));

    #pragma unroll
    for (int qp = 0; qp < RPT / 4; ++qp) {
        uint2 nxt[3];
        if (qp < RPT / 4 - 1) {            // compile-time in unrolled body
            #pragma unroll
            for (int k = 0; k < 3; ++k)
                nxt[k] = __ldg(reinterpret_cast<const uint2*>(
                             fbase + qoff[k] + (qp + 1) * QSTRIDE));
        }

        // convert current quad's fp16 focal values (contain focal*2 + 2)
        float4 f4[3];
        #pragma unroll
        for (int k = 0; k < 3; ++k) {
            float2 lo = __half22float2(*reinterpret_cast<__half2*>(&raw[k].x));
            float2 hi = __half22float2(*reinterpret_cast<__half2*>(&raw[k].y));
            f4[k] = make_float4(lo.x, lo.y, hi.x, hi.y);
        }

        #pragma unroll
        for (int r4 = 0; r4 < 4; ++r4) {
            const int row = row0 + qp * 4 + r4;
            // warp-uniform row loads (broadcast, 1 wavefront each)
            const ulonglong2 rA2 =
                *reinterpret_cast<const ulonglong2*>(&g_rowA[row]);
            const float4 rB = g_rowB[row];       // {x0, y0, -x1, -y1}
            const ulonglong2 rE2 =
                *reinterpret_cast<const ulonglong2*>(&g_rowE[row]);
            const float rarea =
                reinterpret_cast<const float2*>(&rE2.y)->x;

            #pragma unroll
            for (int k = 0; k < 3; ++k) {
                const float f2 = reinterpret_cast<const float*>(&f4[k])[r4];

                // ---- 5*L1: packed diffs (rA=+5c, ta=-5c) ----
                unsigned long long dxy, dzw;
                ADD_F32X2(dxy, rA2.x, taL[k]);
                ADD_F32X2(dzw, rA2.y, taH[k]);
                float d0, d1, d2, d3;
                UNPACK2F(d0, d1, dxy);
                UNPACK2F(d2, d3, dzw);
                float bx = (fabsf(d0) + fabsf(d1)) + (fabsf(d2) + fabsf(d3));

                // ---- intersection via negated-sw form (FMNMX on ALU pipe) --
                float Mx = fmaxf(rB.x, tb[k].x);     // max(x0)
                float My = fmaxf(rB.y, tb[k].y);     // max(y0)
                float Nx = fmaxf(rB.z, tb[k].z);     // max(-x1) = -min(x1)
                float Ny = fmaxf(rB.w, tb[k].w);
                unsigned long long Mxy, Nxy, nswh;
                PACK2F(Mxy, Mx, My);
                PACK2F(Nxy, Nx, Ny);
                ADD_F32X2(nswh, Mxy, Nxy);           // (-sw, -sh)
                float nsw, nsh;
                UNPACK2F(nsw, nsh, nswh);
                float niw = fminf(nsw, 0.0f);        // = -iw   (ALU)
                float nih = fminf(nsh, 0.0f);        // = -ih   (ALU)
                float inter = niw * nih;             // iw*ih

                // ---- enclosing, packed: encwh = (wr+wt) + (-sw,-sh) ----
                unsigned long long wsum, encwh;
                ADD_F32X2(wsum, rE2.x, tE_wh[k]);    // (wr+wt, hr+ht)
                ADD_F32X2(encwh, wsum, nswh);
                float encw, ench;
                UNPACK2F(encw, ench, encwh);
                float enc = encw * ench;

                // uni >= max(area_r, area_t) > 0: no clamps needed
                float uni = (rarea + tarea[k]) - inter;

                // -2*giou = 2 - 2*(inter*enc + uni^2)/(uni*enc); +2 in f2
                float num = fmaf(uni, uni, inter * enc);
                float inv = frcp_approx(uni * enc);

                float res = fmaf(num * inv, -2.0f, f2 + bx);
                __stcs(dstRow + (k << 6), res);      // STG.CS, coalesced
            }
            dstRow += T;   // walk rows (single IADD)
        }

        #pragma unroll
        for (int k = 0; k < 3; ++k) raw[k] = nxt[k];
    }
}

// ---------------------------------------------------------------------------
extern "C" void kernel_launch(void* const* d_in, const int* in_sizes, int n_in,
                              void* d_out, int out_size) {
    const float* pred_logits = (const float*)d_in[0];
    const float* pred_boxes  = (const float*)d_in[1];
    const int*   tgt_ids     = (const int*)d_in[2];
    const float* tgt_boxes   = (const float*)d_in[3];
    float* out = (float*)d_out;

    const int BQ = in_sizes[1] / 4;          // 14400
    const int C  = in_sizes[0] / BQ;         // 91
    const int T  = in_sizes[2];              // 4800

    // division-free prep: one block per row-quad (covers targets too)
    prep_all<<<BQ / 4, 384>>>(pred_logits, pred_boxes, tgt_boxes, tgt_ids,
                              C, T);

    // exact tiling: 4800 = 25*192, 14400 = 225*64
    dim3 grid(T / TGT_TILE, BQ / ROW_TILE);
    cost_kernel<<<grid, 256>>>(out, T);
}